// round 1
// baseline (speedup 1.0000x reference)
#include <cuda_runtime.h>
#include <math.h>

#define NPTS   200000
#define NBINS  512
#define NPART  296      // accumulate-kernel blocks (2 per SM on 148 SMs)
#define TILE   256      // points per shared tile

// Scratch: per-point folded parameters + per-(bin,block) partial sums.
// p1 = (k, mneg, B, A2)   -> u = fma(rt,k,mneg); g = fma(rt,B,A2)
// p2 = (I, wlo, whi, 0)   -> intensity + support window
__device__ float4 g_p1[NPTS];
__device__ float4 g_p2[NPTS];
__device__ float  g_partial[NBINS * NPART];   // bin-major: [bin][block]

__device__ __forceinline__ float ex2f(float x) {
    float y;
    asm("ex2.approx.f32 %0, %1;" : "=f"(y) : "f"(x));
    return y;
}

// ---------------------------------------------------------------------------
// Kernel 1: per-point parameter folding
// ---------------------------------------------------------------------------
__global__ void precompute_kernel(const float* __restrict__ means,
                                  const float* __restrict__ scan_point,
                                  const float* __restrict__ colours,
                                  const float* __restrict__ coefficients,
                                  const float* __restrict__ opacities,
                                  const float* __restrict__ scales)
{
    int i = blockIdx.x * blockDim.x + threadIdx.x;
    if (i >= NPTS) return;

    float sx = scan_point[0], sy = scan_point[1], sz = scan_point[2];
    float dx = means[3 * i + 0] - sx;
    float dy = means[3 * i + 1] - sy;
    float dz = means[3 * i + 2] - sz;
    float r0 = sqrtf(dx * dx + dy * dy + dz * dz);

    float sigma = fmaxf(expf(scales[i]), 0.005f);   // BIN_RES/2 = 0.005
    float sinv  = 1.0f / sigma;

    float c     = coefficients[i];
    float coeff = 1.0f / (1.0f + expf(-c));         // sigmoid

    float op = opacities[i];
    float co = colours[i];
    float I  = (op * op) * (co * co);

    // pdf*(BIN_RES/2) = e * (A + B*diff)
    //   A = 0.005 * coeff * sqrt(0.5/pi) * sinv
    //   B = 0.005 * (1-coeff) * sinv^2
    float A  = 0.005f * coeff * 0.3989422804014327f * sinv;
    float B  = 0.005f * (1.0f - coeff) * sinv * sinv;
    float A2 = A - B * r0;

    // e = exp(-0.5*(diff*sinv)^2) = 2^(-(diff*k)^2), k = sinv*sqrt(0.5*log2(e))
    float k    = 0.84932180028802f * sinv;
    float mneg = -r0 * k;

    // support window: u^2 <= 75  ->  e >= 2^-75 ~ 2.6e-23 (below: skip, negligible)
    float W   = 8.660254037844f / k;
    float wlo = r0 - W;
    float whi = r0 + W;

    g_p1[i] = make_float4(k, mneg, B, A2);
    g_p2[i] = make_float4(I, wlo, whi, 0.0f);
}

// ---------------------------------------------------------------------------
// Kernel 2: accumulate. thread = bin, block = slice of points.
// ---------------------------------------------------------------------------
__global__ void __launch_bounds__(NBINS, 2) accum_kernel()
{
    __shared__ float4 sh1[TILE];
    __shared__ float4 sh2[TILE];

    const int   bin = threadIdx.x;
    const float rt  = 0.005f * (float)(bin + 1);

    // warp-uniform r-range covered by this warp's 32 bins
    const int   wbase = (bin & ~31);
    const float rlo   = 0.005f * (float)(wbase + 1);
    const float rhi   = 0.005f * (float)(wbase + 32);

    const int chunk  = (NPTS + NPART - 1) / NPART;
    const int pstart = blockIdx.x * chunk;
    const int pend   = min(NPTS, pstart + chunk);

    float acc = 0.0f;

    for (int base = pstart; base < pend; base += TILE) {
        const int cnt = min(TILE, pend - base);
        __syncthreads();
        for (int j = threadIdx.x; j < cnt; j += NBINS) {
            sh1[j] = g_p1[base + j];
            sh2[j] = g_p2[base + j];
        }
        __syncthreads();

        #pragma unroll 2
        for (int j = 0; j < cnt; ++j) {
            float4 p2 = sh2[j];                 // (I, wlo, whi, -)
            // warp-uniform skip: this warp's bin range vs point support
            if (p2.z < rlo || p2.y > rhi) continue;
            float4 p1 = sh1[j];                 // (k, mneg, B, A2)
            float u  = fmaf(rt, p1.x, p1.y);    // (r - r0) * k
            float e  = ex2f(-(u * u));          // exp(-0.5*(d/s)^2)
            float gg = fmaf(rt, p1.z, p1.w);    // 0.005 * (c*pdf1 + (1-c)*pdf2) / e
            float pr = __saturatef(e * gg);     // clip(pdf*h/2, 0, 1)
            acc = fmaf(p2.x, pr, acc);          // += intensity * pr
        }
    }

    g_partial[bin * NPART + blockIdx.x] = acc;
}

// ---------------------------------------------------------------------------
// Kernel 3: deterministic reduce over NPART partials + 1/r^2 scaling
// ---------------------------------------------------------------------------
__global__ void reduce_kernel(float* __restrict__ out)
{
    const int b    = blockIdx.x;     // 512 blocks, 32 threads each
    const int lane = threadIdx.x;

    float s = 0.0f;
    for (int j = lane; j < NPART; j += 32)
        s += g_partial[b * NPART + j];

    #pragma unroll
    for (int o = 16; o > 0; o >>= 1)
        s += __shfl_xor_sync(0xFFFFFFFFu, s, o);

    if (lane == 0) {
        float r = 0.005f * (float)(b + 1);
        out[b] = s / (r * r);
    }
}

// ---------------------------------------------------------------------------
extern "C" void kernel_launch(void* const* d_in, const int* in_sizes, int n_in,
                              void* d_out, int out_size)
{
    const float* means        = (const float*)d_in[0];
    const float* scan_point   = (const float*)d_in[1];
    const float* colours      = (const float*)d_in[2];
    const float* coefficients = (const float*)d_in[3];
    const float* opacities    = (const float*)d_in[4];
    const float* scales       = (const float*)d_in[5];
    // d_in[6] = view_id (always 0 since VIEW_NUM == 1)

    float* out = (float*)d_out;

    precompute_kernel<<<(NPTS + 255) / 256, 256>>>(means, scan_point, colours,
                                                   coefficients, opacities, scales);
    accum_kernel<<<NPART, NBINS>>>();
    reduce_kernel<<<NBINS, 32>>>(out);
}